// round 2
// baseline (speedup 1.0000x reference)
#include <cuda_runtime.h>
#include <math.h>

#define NN 100000
#define NE 1600000
#define FEAT 165
#define HID 128

// ---------------- scratch (static __device__, allocation-free) ----------------
__device__ int   g_deg[NN];          // in-degree (edges only, self-loop excluded)
__device__ float g_dinv[NN];         // rsqrt(deg+1)
__device__ int   g_rowptr[NN];       // CSR row start
__device__ int   g_cursor[NN];       // fill cursors
__device__ int   g_bsum[256];        // scan block sums
__device__ int   g_boff[256];        // scan block offsets
__device__ int   g_eidx[NE];         // CSR: src index per edge
__device__ float g_ew[NE];           // CSR: edge norm weight
__device__ float g_xw[(size_t)NN * HID];  // x @ W1  (51.2 MB)
__device__ float g_z[NN * 2];        // relu(h1) @ W2

// ---------------- graph build ----------------
__global__ void k_zero_deg() {
    int i = blockIdx.x * blockDim.x + threadIdx.x;
    if (i < NN) g_deg[i] = 0;
}

__global__ void k_count(const int* __restrict__ ei) {
    int e = blockIdx.x * blockDim.x + threadIdx.x;
    if (e < NE) {
        int d = ei[NE + e];
        if (d >= 0 && d < NN) atomicAdd(&g_deg[d], 1);
    }
}

__global__ void k_dinv() {
    int i = blockIdx.x * blockDim.x + threadIdx.x;
    if (i < NN) g_dinv[i] = rsqrtf((float)g_deg[i] + 1.0f);
}

// 196 blocks x 512 threads: per-block sums
__global__ void k_scanA() {
    __shared__ int sm[16];
    int t = threadIdx.x;
    int i = blockIdx.x * 512 + t;
    int v = (i < NN) ? g_deg[i] : 0;
    #pragma unroll
    for (int off = 16; off > 0; off >>= 1)
        v += __shfl_down_sync(0xffffffffu, v, off);
    if ((t & 31) == 0) sm[t >> 5] = v;
    __syncthreads();
    if (t < 16) {
        int s = sm[t];
        #pragma unroll
        for (int off = 8; off > 0; off >>= 1)
            s += __shfl_down_sync(0xffffu, s, off);
        if (t == 0) g_bsum[blockIdx.x] = s;
    }
}

// 1 block x 256: exclusive scan of block sums
__global__ void k_scanB(int nb) {
    __shared__ int s[256];
    int t = threadIdx.x;
    s[t] = (t < nb) ? g_bsum[t] : 0;
    __syncthreads();
    #pragma unroll
    for (int off = 1; off < 256; off <<= 1) {
        int v = (t >= off) ? s[t - off] : 0;
        __syncthreads();
        s[t] += v;
        __syncthreads();
    }
    g_boff[t] = (t == 0) ? 0 : s[t - 1];
}

// 196 blocks x 512: within-block exclusive scan + offset -> rowptr, cursor
__global__ void k_scanC() {
    __shared__ int s[512];
    int t = threadIdx.x;
    int i = blockIdx.x * 512 + t;
    int v = (i < NN) ? g_deg[i] : 0;
    s[t] = v;
    __syncthreads();
    #pragma unroll
    for (int off = 1; off < 512; off <<= 1) {
        int u = (t >= off) ? s[t - off] : 0;
        __syncthreads();
        s[t] += u;
        __syncthreads();
    }
    int excl = s[t] - v;
    int base = g_boff[blockIdx.x];
    if (i < NN) {
        g_rowptr[i] = base + excl;
        g_cursor[i] = base + excl;
    }
}

__global__ void k_fill(const int* __restrict__ ei) {
    int e = blockIdx.x * blockDim.x + threadIdx.x;
    if (e < NE) {
        int s = ei[e];
        int d = ei[NE + e];
        if (s >= 0 && s < NN && d >= 0 && d < NN) {
            int p = atomicAdd(&g_cursor[d], 1);
            g_eidx[p] = s;
            g_ew[p] = g_dinv[s] * g_dinv[d];
        }
    }
}

// ---------------- GEMM1: xw = x @ W1  (M=100000, N=128, K=165) ----------------
#define BM 128
#define KT 8

__global__ __launch_bounds__(256, 2) void k_gemm1(const float* __restrict__ x,
                                                  const float* __restrict__ W1) {
    __shared__ float As[KT][BM];
    __shared__ float Bs[KT][HID];
    int tid = threadIdx.x;          // 0..255
    int row0 = blockIdx.x * BM;
    int cy = tid >> 4;              // 0..15 -> rows
    int cx = tid & 15;              // 0..15 -> cols
    float acc[8][8];
    #pragma unroll
    for (int i = 0; i < 8; i++)
        #pragma unroll
        for (int j = 0; j < 8; j++) acc[i][j] = 0.f;

    for (int k0 = 0; k0 < FEAT; k0 += KT) {
        // load A tile transposed: As[kk][m] = x[row0+m][k0+kk]
        #pragma unroll
        for (int i = 0; i < 4; i++) {
            int lin = tid + i * 256;
            int m = lin >> 3, kk = lin & 7;
            int r = row0 + m, k = k0 + kk;
            As[kk][m] = (r < NN && k < FEAT) ? x[(size_t)r * FEAT + k] : 0.f;
        }
        // load B tile: Bs[kk][n] = W1[k0+kk][n]
        #pragma unroll
        for (int i = 0; i < 4; i++) {
            int lin = tid + i * 256;
            int n = lin & 127, kk = lin >> 7;
            int k = k0 + kk;
            Bs[kk][n] = (k < FEAT) ? W1[k * HID + n] : 0.f;
        }
        __syncthreads();
        #pragma unroll
        for (int kk = 0; kk < KT; kk++) {
            float a[8], b[8];
            #pragma unroll
            for (int u = 0; u < 8; u++) a[u] = As[kk][cy * 8 + u];
            #pragma unroll
            for (int u = 0; u < 8; u++) b[u] = Bs[kk][cx * 8 + u];
            #pragma unroll
            for (int i = 0; i < 8; i++)
                #pragma unroll
                for (int j = 0; j < 8; j++)
                    acc[i][j] += a[i] * b[j];
        }
        __syncthreads();
    }
    #pragma unroll
    for (int i = 0; i < 8; i++) {
        int r = row0 + cy * 8 + i;
        if (r < NN) {
            float4* dst = (float4*)&g_xw[(size_t)r * HID + cx * 8];
            dst[0] = make_float4(acc[i][0], acc[i][1], acc[i][2], acc[i][3]);
            dst[1] = make_float4(acc[i][4], acc[i][5], acc[i][6], acc[i][7]);
        }
    }
}

// ---------------- layer-1 aggregation, fused bias+relu+(@W2) ----------------
// warp per node; each lane owns 4 channels (float4)
__global__ __launch_bounds__(256) void k_agg1(const float* __restrict__ b1,
                                              const float* __restrict__ W2) {
    __shared__ float w2s[HID * 2];
    int t = threadIdx.x;
    w2s[t] = W2[t];   // 256 threads, 256 elements
    __syncthreads();

    int warp = t >> 5, lane = t & 31;
    int i = blockIdx.x * 8 + warp;
    if (i >= NN) return;

    const float4* xw4 = (const float4*)g_xw;   // 32 float4 per row
    float di = g_dinv[i];
    float sn = di * di;
    float4 acc = xw4[(size_t)i * 32 + lane];   // self loop
    acc.x *= sn; acc.y *= sn; acc.z *= sn; acc.w *= sn;

    int e = g_rowptr[i];
    int end = e + g_deg[i];
    for (; e + 4 <= end; e += 4) {
        int s0 = g_eidx[e],     s1 = g_eidx[e + 1];
        int s2 = g_eidx[e + 2], s3 = g_eidx[e + 3];
        float wa = g_ew[e],     wb = g_ew[e + 1];
        float wc_ = g_ew[e + 2], wd = g_ew[e + 3];
        float4 v0 = xw4[(size_t)s0 * 32 + lane];
        float4 v1 = xw4[(size_t)s1 * 32 + lane];
        float4 v2 = xw4[(size_t)s2 * 32 + lane];
        float4 v3 = xw4[(size_t)s3 * 32 + lane];
        acc.x += wa * v0.x; acc.y += wa * v0.y; acc.z += wa * v0.z; acc.w += wa * v0.w;
        acc.x += wb * v1.x; acc.y += wb * v1.y; acc.z += wb * v1.z; acc.w += wb * v1.w;
        acc.x += wc_ * v2.x; acc.y += wc_ * v2.y; acc.z += wc_ * v2.z; acc.w += wc_ * v2.w;
        acc.x += wd * v3.x; acc.y += wd * v3.y; acc.z += wd * v3.z; acc.w += wd * v3.w;
    }
    for (; e < end; e++) {
        int s = g_eidx[e];
        float w = g_ew[e];
        float4 v = xw4[(size_t)s * 32 + lane];
        acc.x += w * v.x; acc.y += w * v.y; acc.z += w * v.z; acc.w += w * v.w;
    }

    // bias + relu
    float4 bb = ((const float4*)b1)[lane];
    float h0 = fmaxf(acc.x + bb.x, 0.f);
    float h1 = fmaxf(acc.y + bb.y, 0.f);
    float h2 = fmaxf(acc.z + bb.z, 0.f);
    float h3 = fmaxf(acc.w + bb.w, 0.f);

    // partial z = h @ W2 (per lane over its 4 channels)
    int c = lane * 4;
    float z0 = h0 * w2s[(c + 0) * 2 + 0] + h1 * w2s[(c + 1) * 2 + 0]
             + h2 * w2s[(c + 2) * 2 + 0] + h3 * w2s[(c + 3) * 2 + 0];
    float z1 = h0 * w2s[(c + 0) * 2 + 1] + h1 * w2s[(c + 1) * 2 + 1]
             + h2 * w2s[(c + 2) * 2 + 1] + h3 * w2s[(c + 3) * 2 + 1];
    #pragma unroll
    for (int off = 16; off > 0; off >>= 1) {
        z0 += __shfl_down_sync(0xffffffffu, z0, off);
        z1 += __shfl_down_sync(0xffffffffu, z1, off);
    }
    if (lane == 0) {
        ((float2*)g_z)[i] = make_float2(z0, z1);
    }
}

// ---------------- layer-2 aggregation + Wc + sigmoid, thread per node -------
__global__ void k_agg2(const float* __restrict__ b2, const float* __restrict__ Wc,
                       const float* __restrict__ bc, float* __restrict__ out) {
    int i = blockIdx.x * blockDim.x + threadIdx.x;
    if (i >= NN) return;
    const float2* z2 = (const float2*)g_z;
    float di = g_dinv[i];
    float sn = di * di;
    float2 zi = z2[i];
    float a0 = zi.x * sn, a1 = zi.y * sn;   // self loop
    int e = g_rowptr[i];
    int end = e + g_deg[i];
    for (; e < end; e++) {
        int s = g_eidx[e];
        float w = g_ew[e];
        float2 zs = z2[s];
        a0 += w * zs.x;
        a1 += w * zs.y;
    }
    float h0 = fmaxf(a0 + b2[0], 0.f);
    float h1 = fmaxf(a1 + b2[1], 0.f);
    float o = h0 * Wc[0] + h1 * Wc[1] + bc[0];
    out[i] = 1.f / (1.f + expf(-o));
}

// ---------------- launch ----------------
extern "C" void kernel_launch(void* const* d_in, const int* in_sizes, int n_in,
                              void* d_out, int out_size) {
    const float* x  = (const float*)d_in[0];
    const int*   ei = (const int*)d_in[1];
    const float* W1 = (const float*)d_in[2];
    const float* b1 = (const float*)d_in[3];
    const float* W2 = (const float*)d_in[4];
    const float* b2 = (const float*)d_in[5];
    const float* Wc = (const float*)d_in[6];
    const float* bc = (const float*)d_in[7];
    float* out = (float*)d_out;

    const int NB_SCAN = (NN + 511) / 512;   // 196

    k_zero_deg<<<(NN + 255) / 256, 256>>>();
    k_count<<<(NE + 255) / 256, 256>>>(ei);
    k_dinv<<<(NN + 255) / 256, 256>>>();
    k_scanA<<<NB_SCAN, 512>>>();
    k_scanB<<<1, 256>>>(NB_SCAN);
    k_scanC<<<NB_SCAN, 512>>>();
    k_fill<<<(NE + 255) / 256, 256>>>(ei);
    k_gemm1<<<(NN + BM - 1) / BM, 256>>>(x, W1);
    k_agg1<<<(NN + 7) / 8, 256>>>(b1, W2);
    k_agg2<<<(NN + 255) / 256, 256>>>(b2, Wc, bc, out);
}

// round 3
// speedup vs baseline: 1.1564x; 1.1564x over previous
#include <cuda_runtime.h>
#include <cuda_fp16.h>
#include <math.h>

#define NN 100000
#define NE 1600000
#define FEAT 165
#define HID 128

// ---------------- scratch (static __device__, allocation-free) ----------------
__device__ int    g_deg[NN];           // in-degree (edges only)
__device__ float  g_dinv[NN];          // rsqrt(deg+1)
__device__ int    g_rowptr[NN];        // CSR row start
__device__ int    g_cursor[NN];        // fill cursors
__device__ int    g_bsum[256];         // scan block sums
__device__ int    g_boff[256];         // scan block offsets
__device__ int2   g_csr[NE];           // packed CSR entry: (src, __float_as_int(w))
__device__ __half g_xw[(size_t)NN * HID];  // x @ W1 in fp16 (25.6 MB)
__device__ float  g_z[NN * 2];         // relu(h1) @ W2

// ---------------- graph build ----------------
__global__ void k_zero_deg() {
    int i = blockIdx.x * blockDim.x + threadIdx.x;
    if (i < NN) g_deg[i] = 0;
}

__global__ void k_count(const int* __restrict__ ei) {
    int e = blockIdx.x * blockDim.x + threadIdx.x;
    if (e < NE) {
        int d = ei[NE + e];
        if (d >= 0 && d < NN) atomicAdd(&g_deg[d], 1);
    }
}

// 196 blocks x 512 threads: per-block sums; also computes dinv
__global__ void k_scanA() {
    __shared__ int sm[16];
    int t = threadIdx.x;
    int i = blockIdx.x * 512 + t;
    int v = (i < NN) ? g_deg[i] : 0;
    if (i < NN) g_dinv[i] = rsqrtf((float)v + 1.0f);
    int r = v;
    #pragma unroll
    for (int off = 16; off > 0; off >>= 1)
        r += __shfl_down_sync(0xffffffffu, r, off);
    if ((t & 31) == 0) sm[t >> 5] = r;
    __syncthreads();
    if (t < 16) {
        int s = sm[t];
        #pragma unroll
        for (int off = 8; off > 0; off >>= 1)
            s += __shfl_down_sync(0xffffu, s, off);
        if (t == 0) g_bsum[blockIdx.x] = s;
    }
}

// 1 block x 256: exclusive scan of block sums
__global__ void k_scanB(int nb) {
    __shared__ int s[256];
    int t = threadIdx.x;
    s[t] = (t < nb) ? g_bsum[t] : 0;
    __syncthreads();
    #pragma unroll
    for (int off = 1; off < 256; off <<= 1) {
        int v = (t >= off) ? s[t - off] : 0;
        __syncthreads();
        s[t] += v;
        __syncthreads();
    }
    g_boff[t] = (t == 0) ? 0 : s[t - 1];
}

// 196 blocks x 512: within-block exclusive scan + offset -> rowptr, cursor
__global__ void k_scanC() {
    __shared__ int s[512];
    int t = threadIdx.x;
    int i = blockIdx.x * 512 + t;
    int v = (i < NN) ? g_deg[i] : 0;
    s[t] = v;
    __syncthreads();
    #pragma unroll
    for (int off = 1; off < 512; off <<= 1) {
        int u = (t >= off) ? s[t - off] : 0;
        __syncthreads();
        s[t] += u;
        __syncthreads();
    }
    int excl = s[t] - v;
    int base = g_boff[blockIdx.x];
    if (i < NN) {
        g_rowptr[i] = base + excl;
        g_cursor[i] = base + excl;
    }
}

__global__ void k_fill(const int* __restrict__ ei) {
    int e = blockIdx.x * blockDim.x + threadIdx.x;
    if (e < NE) {
        int s = ei[e];
        int d = ei[NE + e];
        if (s >= 0 && s < NN && d >= 0 && d < NN) {
            int p = atomicAdd(&g_cursor[d], 1);
            float w = g_dinv[s] * g_dinv[d];
            g_csr[p] = make_int2(s, __float_as_int(w));
        }
    }
}

// ---------------- GEMM1: xw = x @ W1  (M=100000, N=128, K=165), fp16 out ----
#define BM 128
#define KT 8

__global__ __launch_bounds__(256, 2) void k_gemm1(const float* __restrict__ x,
                                                  const float* __restrict__ W1) {
    __shared__ float As[KT][BM];
    __shared__ float Bs[KT][HID];
    int tid = threadIdx.x;          // 0..255
    int row0 = blockIdx.x * BM;
    int cy = tid >> 4;              // 0..15 -> rows
    int cx = tid & 15;              // 0..15 -> cols
    float acc[8][8];
    #pragma unroll
    for (int i = 0; i < 8; i++)
        #pragma unroll
        for (int j = 0; j < 8; j++) acc[i][j] = 0.f;

    for (int k0 = 0; k0 < FEAT; k0 += KT) {
        #pragma unroll
        for (int i = 0; i < 4; i++) {
            int lin = tid + i * 256;
            int m = lin >> 3, kk = lin & 7;
            int r = row0 + m, k = k0 + kk;
            As[kk][m] = (r < NN && k < FEAT) ? x[(size_t)r * FEAT + k] : 0.f;
        }
        #pragma unroll
        for (int i = 0; i < 4; i++) {
            int lin = tid + i * 256;
            int n = lin & 127, kk = lin >> 7;
            int k = k0 + kk;
            Bs[kk][n] = (k < FEAT) ? W1[k * HID + n] : 0.f;
        }
        __syncthreads();
        #pragma unroll
        for (int kk = 0; kk < KT; kk++) {
            float a[8], b[8];
            #pragma unroll
            for (int u = 0; u < 8; u++) a[u] = As[kk][cy * 8 + u];
            #pragma unroll
            for (int u = 0; u < 8; u++) b[u] = Bs[kk][cx * 8 + u];
            #pragma unroll
            for (int i = 0; i < 8; i++)
                #pragma unroll
                for (int j = 0; j < 8; j++)
                    acc[i][j] += a[i] * b[j];
        }
        __syncthreads();
    }
    #pragma unroll
    for (int i = 0; i < 8; i++) {
        int r = row0 + cy * 8 + i;
        if (r < NN) {
            __half2 h0 = __floats2half2_rn(acc[i][0], acc[i][1]);
            __half2 h1 = __floats2half2_rn(acc[i][2], acc[i][3]);
            __half2 h2 = __floats2half2_rn(acc[i][4], acc[i][5]);
            __half2 h3 = __floats2half2_rn(acc[i][6], acc[i][7]);
            uint4 pk;
            pk.x = *(unsigned*)&h0; pk.y = *(unsigned*)&h1;
            pk.z = *(unsigned*)&h2; pk.w = *(unsigned*)&h3;
            *(uint4*)&g_xw[(size_t)r * HID + cx * 8] = pk;
        }
    }
}

// ---------------- layer-1 aggregation, fused bias+relu+(@W2) ----------------
// warp per node; lane owns 4 channels (2x half2)
__global__ __launch_bounds__(256) void k_agg1(const float* __restrict__ b1,
                                              const float* __restrict__ W2) {
    __shared__ float w2s[HID * 2];
    int t = threadIdx.x;
    w2s[t] = W2[t];   // 256 threads, 256 elements
    __syncthreads();

    int warp = t >> 5, lane = t & 31;
    int i = blockIdx.x * 8 + warp;
    if (i >= NN) return;

    const uint2* xw2 = (const uint2*)g_xw;   // 32 uint2 (4 halves) per row
    float di = g_dinv[i];
    float sn = di * di;
    uint2 sv = xw2[(size_t)i * 32 + lane];   // self loop
    float2 s0 = __half22float2(*(__half2*)&sv.x);
    float2 s1 = __half22float2(*(__half2*)&sv.y);
    float a0 = sn * s0.x, a1 = sn * s0.y, a2 = sn * s1.x, a3 = sn * s1.y;

    int e = g_rowptr[i];
    int end = e + g_deg[i];
    for (; e + 4 <= end; e += 4) {
        int2 c0 = g_csr[e],     c1 = g_csr[e + 1];
        int2 c2 = g_csr[e + 2], c3 = g_csr[e + 3];
        uint2 v0 = xw2[(size_t)c0.x * 32 + lane];
        uint2 v1 = xw2[(size_t)c1.x * 32 + lane];
        uint2 v2 = xw2[(size_t)c2.x * 32 + lane];
        uint2 v3 = xw2[(size_t)c3.x * 32 + lane];
        float wa = __int_as_float(c0.y), wb = __int_as_float(c1.y);
        float wc_ = __int_as_float(c2.y), wd = __int_as_float(c3.y);
        float2 f;
        f = __half22float2(*(__half2*)&v0.x); a0 += wa * f.x; a1 += wa * f.y;
        f = __half22float2(*(__half2*)&v0.y); a2 += wa * f.x; a3 += wa * f.y;
        f = __half22float2(*(__half2*)&v1.x); a0 += wb * f.x; a1 += wb * f.y;
        f = __half22float2(*(__half2*)&v1.y); a2 += wb * f.x; a3 += wb * f.y;
        f = __half22float2(*(__half2*)&v2.x); a0 += wc_ * f.x; a1 += wc_ * f.y;
        f = __half22float2(*(__half2*)&v2.y); a2 += wc_ * f.x; a3 += wc_ * f.y;
        f = __half22float2(*(__half2*)&v3.x); a0 += wd * f.x; a1 += wd * f.y;
        f = __half22float2(*(__half2*)&v3.y); a2 += wd * f.x; a3 += wd * f.y;
    }
    for (; e < end; e++) {
        int2 c = g_csr[e];
        float w = __int_as_float(c.y);
        uint2 v = xw2[(size_t)c.x * 32 + lane];
        float2 f;
        f = __half22float2(*(__half2*)&v.x); a0 += w * f.x; a1 += w * f.y;
        f = __half22float2(*(__half2*)&v.y); a2 += w * f.x; a3 += w * f.y;
    }

    // bias + relu
    float4 bb = ((const float4*)b1)[lane];
    float h0 = fmaxf(a0 + bb.x, 0.f);
    float h1 = fmaxf(a1 + bb.y, 0.f);
    float h2 = fmaxf(a2 + bb.z, 0.f);
    float h3 = fmaxf(a3 + bb.w, 0.f);

    // partial z = h @ W2 over this lane's 4 channels
    int c = lane * 4;
    float z0 = h0 * w2s[(c + 0) * 2 + 0] + h1 * w2s[(c + 1) * 2 + 0]
             + h2 * w2s[(c + 2) * 2 + 0] + h3 * w2s[(c + 3) * 2 + 0];
    float z1 = h0 * w2s[(c + 0) * 2 + 1] + h1 * w2s[(c + 1) * 2 + 1]
             + h2 * w2s[(c + 2) * 2 + 1] + h3 * w2s[(c + 3) * 2 + 1];
    #pragma unroll
    for (int off = 16; off > 0; off >>= 1) {
        z0 += __shfl_down_sync(0xffffffffu, z0, off);
        z1 += __shfl_down_sync(0xffffffffu, z1, off);
    }
    if (lane == 0) {
        ((float2*)g_z)[i] = make_float2(z0, z1);
    }
}

// ---------------- layer-2 aggregation + Wc + sigmoid, thread per node -------
__global__ void k_agg2(const float* __restrict__ b2, const float* __restrict__ Wc,
                       const float* __restrict__ bc, float* __restrict__ out) {
    int i = blockIdx.x * blockDim.x + threadIdx.x;
    if (i >= NN) return;
    const float2* z2 = (const float2*)g_z;
    float di = g_dinv[i];
    float sn = di * di;
    float2 zi = z2[i];
    float a0 = zi.x * sn, a1 = zi.y * sn;   // self loop
    int e = g_rowptr[i];
    int end = e + g_deg[i];
    for (; e < end; e++) {
        int2 c = g_csr[e];
        float w = __int_as_float(c.y);
        float2 zs = z2[c.x];
        a0 += w * zs.x;
        a1 += w * zs.y;
    }
    float h0 = fmaxf(a0 + b2[0], 0.f);
    float h1 = fmaxf(a1 + b2[1], 0.f);
    float o = h0 * Wc[0] + h1 * Wc[1] + bc[0];
    out[i] = 1.f / (1.f + expf(-o));
}

// ---------------- launch ----------------
extern "C" void kernel_launch(void* const* d_in, const int* in_sizes, int n_in,
                              void* d_out, int out_size) {
    const float* x  = (const float*)d_in[0];
    const int*   ei = (const int*)d_in[1];
    const float* W1 = (const float*)d_in[2];
    const float* b1 = (const float*)d_in[3];
    const float* W2 = (const float*)d_in[4];
    const float* b2 = (const float*)d_in[5];
    const float* Wc = (const float*)d_in[6];
    const float* bc = (const float*)d_in[7];
    float* out = (float*)d_out;

    const int NB_SCAN = (NN + 511) / 512;   // 196

    k_zero_deg<<<(NN + 255) / 256, 256>>>();
    k_count<<<(NE + 255) / 256, 256>>>(ei);
    k_scanA<<<NB_SCAN, 512>>>();
    k_scanB<<<1, 256>>>(NB_SCAN);
    k_scanC<<<NB_SCAN, 512>>>();
    k_fill<<<(NE + 255) / 256, 256>>>(ei);
    k_gemm1<<<(NN + BM - 1) / BM, 256>>>(x, W1);
    k_agg1<<<(NN + 7) / 8, 256>>>(b1, W2);
    k_agg2<<<(NN + 255) / 256, 256>>>(b2, Wc, bc, out);
}

// round 5
// speedup vs baseline: 1.1935x; 1.0321x over previous
#include <cuda_runtime.h>
#include <cuda_fp16.h>
#include <mma.h>
#include <math.h>

using namespace nvcuda;

#define NN 100000
#define NE 1600000
#define FEAT 165
#define HID 128
#define NBT 196          // scan tiles (196 * 512 >= NN)

// ---------------- scratch (static __device__, allocation-free) ----------------
__device__ int      g_deg[NN];
__device__ float    g_dinv[NN];
__device__ int      g_rowptr[NN];
__device__ int      g_cursor[NN];
__device__ int      g_tile_ctr;
__device__ unsigned g_tile_state[NBT];
__device__ int2     g_csr[NE];              // (src, bits(w))
__device__ __half   g_xw[(size_t)NN * HID]; // x @ W1 in fp16 (25.6 MB)
__device__ float    g_z[NN * 2];

#define ST_AGG 0x40000000u
#define ST_PRE 0x80000000u
#define ST_VAL 0x3FFFFFFFu

// ---------------- init: zero degrees + scan state ----------------
__global__ void k_init() {
    int i = blockIdx.x * blockDim.x + threadIdx.x;
    if (i < NN) g_deg[i] = 0;
    if (i < NBT) g_tile_state[i] = 0;
    if (i == 0) g_tile_ctr = 0;
}

__global__ void k_count(const int* __restrict__ ei) {
    int e = blockIdx.x * blockDim.x + threadIdx.x;
    if (e < NE) {
        int d = ei[NE + e];
        if (d >= 0 && d < NN) atomicAdd(&g_deg[d], 1);
    }
}

// ---------------- single-pass scan (decoupled lookback) + dinv ----------------
__global__ void k_scan() {
    __shared__ int s[512];
    __shared__ int sh_bid;
    __shared__ int sh_excl;
    int t = threadIdx.x;
    if (t == 0) sh_bid = atomicAdd(&g_tile_ctr, 1);
    __syncthreads();
    int bid = sh_bid;
    int i = bid * 512 + t;
    int v = (i < NN) ? g_deg[i] : 0;
    if (i < NN) g_dinv[i] = rsqrtf((float)v + 1.0f);
    s[t] = v;
    __syncthreads();
    #pragma unroll
    for (int off = 1; off < 512; off <<= 1) {
        int u = (t >= off) ? s[t - off] : 0;
        __syncthreads();
        s[t] += u;
        __syncthreads();
    }
    int incl = s[t];
    int total = s[511];
    if (t == 0) {
        if (bid == 0) {
            __threadfence();
            atomicExch(&g_tile_state[0], ST_PRE | (unsigned)total);
            sh_excl = 0;
        } else {
            __threadfence();
            atomicExch(&g_tile_state[bid], ST_AGG | (unsigned)total);
            int excl = 0;
            for (int j = bid - 1; j >= 0; j--) {
                unsigned st;
                do { st = atomicAdd(&g_tile_state[j], 0u); } while (!(st & (ST_AGG | ST_PRE)));
                excl += (int)(st & ST_VAL);
                if (st & ST_PRE) break;
            }
            __threadfence();
            atomicExch(&g_tile_state[bid], ST_PRE | (unsigned)(excl + total));
            sh_excl = excl;
        }
    }
    __syncthreads();
    if (i < NN) {
        int rp = sh_excl + incl - v;
        g_rowptr[i] = rp;
        g_cursor[i] = rp;
    }
}

__global__ void k_fill(const int* __restrict__ ei) {
    int e = blockIdx.x * blockDim.x + threadIdx.x;
    if (e < NE) {
        int s = ei[e];
        int d = ei[NE + e];
        if (s >= 0 && s < NN && d >= 0 && d < NN) {
            int p = atomicAdd(&g_cursor[d], 1);
            float w = g_dinv[s] * g_dinv[d];
            g_csr[p] = make_int2(s, __float_as_int(w));
        }
    }
}

// ---------------- GEMM1 (tf32 wmma): xw = x @ W1, fp16 out ----------------
// block tile 128x128, 8 warps (each 32x64), K-tiles of 32 (4 mma k-steps)
// static smem only: As 18KB + Bs 16.5KB + per-warp C scratch 8KB = 42.8KB
#define ASTRIDE 36
#define BSTRIDE 132

__global__ __launch_bounds__(256) void k_gemm1(const float* __restrict__ x,
                                               const float* __restrict__ W1) {
    __shared__ float As[128 * ASTRIDE];
    __shared__ float Bs[32 * BSTRIDE];
    __shared__ float Cs[8][16 * 16];    // per-warp fragment scratch

    int tid = threadIdx.x;
    int w = tid >> 5;
    int lane = tid & 31;
    int warp_m = w & 3;        // 0..3 -> 32-row band
    int warp_n = w >> 2;       // 0..1 -> 64-col band
    int row0 = blockIdx.x * 128;

    wmma::fragment<wmma::accumulator, 16, 16, 8, float> cf[2][4];
    #pragma unroll
    for (int mi = 0; mi < 2; mi++)
        #pragma unroll
        for (int ni = 0; ni < 4; ni++)
            wmma::fill_fragment(cf[mi][ni], 0.0f);

    for (int k0 = 0; k0 < FEAT; k0 += 32) {
        #pragma unroll
        for (int i = 0; i < 16; i++) {
            int idx = tid + i * 256;
            int m = idx >> 5, k = idx & 31;
            int r = row0 + m, kk = k0 + k;
            As[m * ASTRIDE + k] = (r < NN && kk < FEAT) ? x[(size_t)r * FEAT + kk] : 0.f;
        }
        #pragma unroll
        for (int i = 0; i < 16; i++) {
            int idx = tid + i * 256;
            int k = idx >> 7, n = idx & 127;
            int kk = k0 + k;
            Bs[k * BSTRIDE + n] = (kk < FEAT) ? W1[kk * HID + n] : 0.f;
        }
        __syncthreads();
        #pragma unroll
        for (int ks = 0; ks < 4; ks++) {
            wmma::fragment<wmma::matrix_a, 16, 16, 8, wmma::precision::tf32, wmma::row_major> af[2];
            wmma::fragment<wmma::matrix_b, 16, 16, 8, wmma::precision::tf32, wmma::row_major> bf[4];
            #pragma unroll
            for (int mi = 0; mi < 2; mi++) {
                wmma::load_matrix_sync(af[mi], As + (warp_m * 32 + mi * 16) * ASTRIDE + ks * 8, ASTRIDE);
                #pragma unroll
                for (int j = 0; j < af[mi].num_elements; j++)
                    af[mi].x[j] = wmma::__float_to_tf32(af[mi].x[j]);
            }
            #pragma unroll
            for (int ni = 0; ni < 4; ni++) {
                wmma::load_matrix_sync(bf[ni], Bs + (ks * 8) * BSTRIDE + warp_n * 64 + ni * 16, BSTRIDE);
                #pragma unroll
                for (int j = 0; j < bf[ni].num_elements; j++)
                    bf[ni].x[j] = wmma::__float_to_tf32(bf[ni].x[j]);
            }
            #pragma unroll
            for (int mi = 0; mi < 2; mi++)
                #pragma unroll
                for (int ni = 0; ni < 4; ni++)
                    wmma::mma_sync(cf[mi][ni], af[mi], bf[ni], cf[mi][ni]);
        }
        __syncthreads();
    }

    // epilogue: per-fragment through per-warp smem scratch -> fp16 global
    #pragma unroll
    for (int mi = 0; mi < 2; mi++) {
        #pragma unroll
        for (int ni = 0; ni < 4; ni++) {
            wmma::store_matrix_sync(Cs[w], cf[mi][ni], 16, wmma::mem_row_major);
            __syncwarp();
            // 256 floats, 32 lanes -> 8 floats (8 halves, one uint4) per lane
            int fr = lane >> 1;            // 0..15 fragment row
            int fc = (lane & 1) * 8;       // 0 or 8
            int r = row0 + warp_m * 32 + mi * 16 + fr;
            if (r < NN) {
                const float* src = &Cs[w][fr * 16 + fc];
                __half2 h0 = __floats2half2_rn(src[0], src[1]);
                __half2 h1 = __floats2half2_rn(src[2], src[3]);
                __half2 h2 = __floats2half2_rn(src[4], src[5]);
                __half2 h3 = __floats2half2_rn(src[6], src[7]);
                uint4 pk;
                pk.x = *(unsigned*)&h0; pk.y = *(unsigned*)&h1;
                pk.z = *(unsigned*)&h2; pk.w = *(unsigned*)&h3;
                *(uint4*)&g_xw[(size_t)r * HID + warp_n * 64 + ni * 16 + fc] = pk;
            }
            __syncwarp();
        }
    }
}

// ---------------- layer-1 aggregation, fused bias+relu+(@W2) ----------------
__global__ __launch_bounds__(256) void k_agg1(const float* __restrict__ b1,
                                              const float* __restrict__ W2) {
    __shared__ float w2s[HID * 2];
    int t = threadIdx.x;
    w2s[t] = W2[t];
    __syncthreads();

    int warp = t >> 5, lane = t & 31;
    int i = blockIdx.x * 8 + warp;
    if (i >= NN) return;

    const uint2* xw2 = (const uint2*)g_xw;   // 32 uint2 (4 halves) per row
    float di = g_dinv[i];
    float sn = di * di;
    uint2 sv = xw2[(size_t)i * 32 + lane];
    float2 s0 = __half22float2(*(__half2*)&sv.x);
    float2 s1 = __half22float2(*(__half2*)&sv.y);
    float a0 = sn * s0.x, a1 = sn * s0.y, a2 = sn * s1.x, a3 = sn * s1.y;

    int e = g_rowptr[i];
    int end = e + g_deg[i];
    for (; e + 4 <= end; e += 4) {
        int2 c0 = g_csr[e],     c1 = g_csr[e + 1];
        int2 c2 = g_csr[e + 2], c3 = g_csr[e + 3];
        uint2 v0 = xw2[(size_t)c0.x * 32 + lane];
        uint2 v1 = xw2[(size_t)c1.x * 32 + lane];
        uint2 v2 = xw2[(size_t)c2.x * 32 + lane];
        uint2 v3 = xw2[(size_t)c3.x * 32 + lane];
        float wa = __int_as_float(c0.y), wb = __int_as_float(c1.y);
        float wc_ = __int_as_float(c2.y), wd = __int_as_float(c3.y);
        float2 f;
        f = __half22float2(*(__half2*)&v0.x); a0 += wa * f.x; a1 += wa * f.y;
        f = __half22float2(*(__half2*)&v0.y); a2 += wa * f.x; a3 += wa * f.y;
        f = __half22float2(*(__half2*)&v1.x); a0 += wb * f.x; a1 += wb * f.y;
        f = __half22float2(*(__half2*)&v1.y); a2 += wb * f.x; a3 += wb * f.y;
        f = __half22float2(*(__half2*)&v2.x); a0 += wc_ * f.x; a1 += wc_ * f.y;
        f = __half22float2(*(__half2*)&v2.y); a2 += wc_ * f.x; a3 += wc_ * f.y;
        f = __half22float2(*(__half2*)&v3.x); a0 += wd * f.x; a1 += wd * f.y;
        f = __half22float2(*(__half2*)&v3.y); a2 += wd * f.x; a3 += wd * f.y;
    }
    for (; e < end; e++) {
        int2 c = g_csr[e];
        float w = __int_as_float(c.y);
        uint2 v = xw2[(size_t)c.x * 32 + lane];
        float2 f;
        f = __half22float2(*(__half2*)&v.x); a0 += w * f.x; a1 += w * f.y;
        f = __half22float2(*(__half2*)&v.y); a2 += w * f.x; a3 += w * f.y;
    }

    float4 bb = ((const float4*)b1)[lane];
    float h0 = fmaxf(a0 + bb.x, 0.f);
    float h1 = fmaxf(a1 + bb.y, 0.f);
    float h2 = fmaxf(a2 + bb.z, 0.f);
    float h3 = fmaxf(a3 + bb.w, 0.f);

    int c = lane * 4;
    float z0 = h0 * w2s[(c + 0) * 2 + 0] + h1 * w2s[(c + 1) * 2 + 0]
             + h2 * w2s[(c + 2) * 2 + 0] + h3 * w2s[(c + 3) * 2 + 0];
    float z1 = h0 * w2s[(c + 0) * 2 + 1] + h1 * w2s[(c + 1) * 2 + 1]
             + h2 * w2s[(c + 2) * 2 + 1] + h3 * w2s[(c + 3) * 2 + 1];
    #pragma unroll
    for (int off = 16; off > 0; off >>= 1) {
        z0 += __shfl_down_sync(0xffffffffu, z0, off);
        z1 += __shfl_down_sync(0xffffffffu, z1, off);
    }
    if (lane == 0) ((float2*)g_z)[i] = make_float2(z0, z1);
}

// ---------------- layer-2 aggregation + Wc + sigmoid ----------------
__global__ void k_agg2(const float* __restrict__ b2, const float* __restrict__ Wc,
                       const float* __restrict__ bc, float* __restrict__ out) {
    int i = blockIdx.x * blockDim.x + threadIdx.x;
    if (i >= NN) return;
    const float2* z2 = (const float2*)g_z;
    float di = g_dinv[i];
    float sn = di * di;
    float2 zi = z2[i];
    float a0 = zi.x * sn, a1 = zi.y * sn;
    int e = g_rowptr[i];
    int end = e + g_deg[i];
    for (; e < end; e++) {
        int2 c = g_csr[e];
        float w = __int_as_float(c.y);
        float2 zs = z2[c.x];
        a0 += w * zs.x;
        a1 += w * zs.y;
    }
    float h0 = fmaxf(a0 + b2[0], 0.f);
    float h1 = fmaxf(a1 + b2[1], 0.f);
    float o = h0 * Wc[0] + h1 * Wc[1] + bc[0];
    out[i] = 1.f / (1.f + expf(-o));
}

// ---------------- launch (single stream, no host objects) ----------------
extern "C" void kernel_launch(void* const* d_in, const int* in_sizes, int n_in,
                              void* d_out, int out_size) {
    const float* x  = (const float*)d_in[0];
    const int*   ei = (const int*)d_in[1];
    const float* W1 = (const float*)d_in[2];
    const float* b1 = (const float*)d_in[3];
    const float* W2 = (const float*)d_in[4];
    const float* b2 = (const float*)d_in[5];
    const float* Wc = (const float*)d_in[6];
    const float* bc = (const float*)d_in[7];
    float* out = (float*)d_out;

    k_init<<<(NN + 255) / 256, 256>>>();
    k_count<<<(NE + 255) / 256, 256>>>(ei);
    k_scan<<<NBT, 512>>>();
    k_fill<<<(NE + 255) / 256, 256>>>(ei);
    k_gemm1<<<(NN + 127) / 128, 256>>>(x, W1);
    k_agg1<<<(NN + 7) / 8, 256>>>(b1, W2);
    k_agg2<<<(NN + 255) / 256, 256>>>(b2, Wc, bc, out);
}

// round 6
// speedup vs baseline: 1.2335x; 1.0335x over previous
#include <cuda_runtime.h>
#include <cuda_fp16.h>
#include <mma.h>
#include <math.h>

using namespace nvcuda;

#define NN 100000
#define NE 1600000
#define FEAT 165
#define HID 128
#define NBT 196          // scan tiles (196 * 512 >= NN)
#define GEMM_NB 782      // ceil(100000/128)
#define FILL_NB 782      // ceil(200000 threads / 256), 8 edges per thread

// ---------------- scratch (static __device__, allocation-free) ----------------
__device__ int      g_deg[NN];
__device__ float    g_dinv[NN];
__device__ int      g_rowptr[NN];
__device__ int      g_cursor[NN];
__device__ int      g_tile_ctr;
__device__ unsigned g_tile_state[NBT];
__device__ int2     g_csr[NE];              // (src, bits(w))
__device__ __half   g_xw[(size_t)NN * HID]; // x @ W1 in fp16 (25.6 MB)
__device__ float    g_z[NN * 2];

#define ST_AGG 0x40000000u
#define ST_PRE 0x80000000u
#define ST_VAL 0x3FFFFFFFu

// ---------------- init: zero degrees + scan state ----------------
__global__ void k_init() {
    int i = blockIdx.x * blockDim.x + threadIdx.x;
    if (i < NN) g_deg[i] = 0;
    if (i < NBT) g_tile_state[i] = 0;
    if (i == 0) g_tile_ctr = 0;
}

// 4 edges per thread, int4 edge reads
__global__ void k_count(const int* __restrict__ ei) {
    int t = blockIdx.x * blockDim.x + threadIdx.x;
    int e0 = t * 4;
    if (e0 < NE) {
        int4 d4 = *(const int4*)&ei[NE + e0];
        if (d4.x >= 0 && d4.x < NN) atomicAdd(&g_deg[d4.x], 1);
        if (d4.y >= 0 && d4.y < NN) atomicAdd(&g_deg[d4.y], 1);
        if (d4.z >= 0 && d4.z < NN) atomicAdd(&g_deg[d4.z], 1);
        if (d4.w >= 0 && d4.w < NN) atomicAdd(&g_deg[d4.w], 1);
    }
}

// ---------------- single-pass scan (decoupled lookback) + dinv ----------------
__global__ void k_scan() {
    __shared__ int s[512];
    __shared__ int sh_bid;
    __shared__ int sh_excl;
    int t = threadIdx.x;
    if (t == 0) sh_bid = atomicAdd(&g_tile_ctr, 1);
    __syncthreads();
    int bid = sh_bid;
    int i = bid * 512 + t;
    int v = (i < NN) ? g_deg[i] : 0;
    if (i < NN) g_dinv[i] = rsqrtf((float)v + 1.0f);
    s[t] = v;
    __syncthreads();
    #pragma unroll
    for (int off = 1; off < 512; off <<= 1) {
        int u = (t >= off) ? s[t - off] : 0;
        __syncthreads();
        s[t] += u;
        __syncthreads();
    }
    int incl = s[t];
    int total = s[511];
    if (t == 0) {
        if (bid == 0) {
            __threadfence();
            atomicExch(&g_tile_state[0], ST_PRE | (unsigned)total);
            sh_excl = 0;
        } else {
            __threadfence();
            atomicExch(&g_tile_state[bid], ST_AGG | (unsigned)total);
            int excl = 0;
            for (int j = bid - 1; j >= 0; j--) {
                unsigned st;
                do { st = atomicAdd(&g_tile_state[j], 0u); } while (!(st & (ST_AGG | ST_PRE)));
                excl += (int)(st & ST_VAL);
                if (st & ST_PRE) break;
            }
            __threadfence();
            atomicExch(&g_tile_state[bid], ST_PRE | (unsigned)(excl + total));
            sh_excl = excl;
        }
    }
    __syncthreads();
    if (i < NN) {
        int rp = sh_excl + incl - v;
        g_rowptr[i] = rp;
        g_cursor[i] = rp;
    }
}

// ---------------- fused fill + GEMM1 (independent work, one launch) ----------
#define ASTRIDE 36
#define BSTRIDE 132

__global__ __launch_bounds__(256) void k_fill_gemm(const int* __restrict__ ei,
                                                   const float* __restrict__ x,
                                                   const float* __restrict__ W1) {
    __shared__ float As[128 * ASTRIDE];
    __shared__ float Bs[32 * BSTRIDE];
    __shared__ float Cs[8][16 * 16];

    int tid = threadIdx.x;

    if (blockIdx.x >= GEMM_NB) {
        // ---------- fill branch: 8 edges per thread, int4 reads ----------
        int t8 = (blockIdx.x - GEMM_NB) * 256 + tid;
        int e0 = t8 * 8;
        if (e0 < NE) {
            int4 sa = *(const int4*)&ei[e0];
            int4 sb = *(const int4*)&ei[e0 + 4];
            int4 da = *(const int4*)&ei[NE + e0];
            int4 db = *(const int4*)&ei[NE + e0 + 4];
            int src[8] = {sa.x, sa.y, sa.z, sa.w, sb.x, sb.y, sb.z, sb.w};
            int dst[8] = {da.x, da.y, da.z, da.w, db.x, db.y, db.z, db.w};
            float ds[8], dd[8];
            #pragma unroll
            for (int j = 0; j < 8; j++) {
                bool ok = (src[j] >= 0 && src[j] < NN && dst[j] >= 0 && dst[j] < NN);
                ds[j] = ok ? g_dinv[src[j]] : 0.f;
                dd[j] = ok ? g_dinv[dst[j]] : 0.f;
                if (!ok) dst[j] = -1;
            }
            #pragma unroll
            for (int j = 0; j < 8; j++) {
                if (dst[j] >= 0) {
                    int p = atomicAdd(&g_cursor[dst[j]], 1);
                    g_csr[p] = make_int2(src[j], __float_as_int(ds[j] * dd[j]));
                }
            }
        }
        return;
    }

    // ---------- GEMM branch: 128x128 block tile, tf32 wmma ----------
    int w = tid >> 5;
    int lane = tid & 31;
    int warp_m = w & 3;
    int warp_n = w >> 2;
    int row0 = blockIdx.x * 128;

    wmma::fragment<wmma::accumulator, 16, 16, 8, float> cf[2][4];
    #pragma unroll
    for (int mi = 0; mi < 2; mi++)
        #pragma unroll
        for (int ni = 0; ni < 4; ni++)
            wmma::fill_fragment(cf[mi][ni], 0.0f);

    for (int k0 = 0; k0 < FEAT; k0 += 32) {
        #pragma unroll
        for (int i = 0; i < 16; i++) {
            int idx = tid + i * 256;
            int m = idx >> 5, k = idx & 31;
            int r = row0 + m, kk = k0 + k;
            As[m * ASTRIDE + k] = (r < NN && kk < FEAT) ? x[(size_t)r * FEAT + kk] : 0.f;
        }
        #pragma unroll
        for (int i = 0; i < 16; i++) {
            int idx = tid + i * 256;
            int k = idx >> 7, n = idx & 127;
            int kk = k0 + k;
            Bs[k * BSTRIDE + n] = (kk < FEAT) ? W1[kk * HID + n] : 0.f;
        }
        __syncthreads();
        #pragma unroll
        for (int ks = 0; ks < 4; ks++) {
            wmma::fragment<wmma::matrix_a, 16, 16, 8, wmma::precision::tf32, wmma::row_major> af[2];
            wmma::fragment<wmma::matrix_b, 16, 16, 8, wmma::precision::tf32, wmma::row_major> bf[4];
            #pragma unroll
            for (int mi = 0; mi < 2; mi++) {
                wmma::load_matrix_sync(af[mi], As + (warp_m * 32 + mi * 16) * ASTRIDE + ks * 8, ASTRIDE);
                #pragma unroll
                for (int j = 0; j < af[mi].num_elements; j++)
                    af[mi].x[j] = wmma::__float_to_tf32(af[mi].x[j]);
            }
            #pragma unroll
            for (int ni = 0; ni < 4; ni++) {
                wmma::load_matrix_sync(bf[ni], Bs + (ks * 8) * BSTRIDE + warp_n * 64 + ni * 16, BSTRIDE);
                #pragma unroll
                for (int j = 0; j < bf[ni].num_elements; j++)
                    bf[ni].x[j] = wmma::__float_to_tf32(bf[ni].x[j]);
            }
            #pragma unroll
            for (int mi = 0; mi < 2; mi++)
                #pragma unroll
                for (int ni = 0; ni < 4; ni++)
                    wmma::mma_sync(cf[mi][ni], af[mi], bf[ni], cf[mi][ni]);
        }
        __syncthreads();
    }

    #pragma unroll
    for (int mi = 0; mi < 2; mi++) {
        #pragma unroll
        for (int ni = 0; ni < 4; ni++) {
            wmma::store_matrix_sync(Cs[w], cf[mi][ni], 16, wmma::mem_row_major);
            __syncwarp();
            int fr = lane >> 1;
            int fc = (lane & 1) * 8;
            int r = row0 + warp_m * 32 + mi * 16 + fr;
            if (r < NN) {
                const float* src = &Cs[w][fr * 16 + fc];
                __half2 h0 = __floats2half2_rn(src[0], src[1]);
                __half2 h1 = __floats2half2_rn(src[2], src[3]);
                __half2 h2 = __floats2half2_rn(src[4], src[5]);
                __half2 h3 = __floats2half2_rn(src[6], src[7]);
                uint4 pk;
                pk.x = *(unsigned*)&h0; pk.y = *(unsigned*)&h1;
                pk.z = *(unsigned*)&h2; pk.w = *(unsigned*)&h3;
                *(uint4*)&g_xw[(size_t)r * HID + warp_n * 64 + ni * 16 + fc] = pk;
            }
            __syncwarp();
        }
    }
}

// ---------------- layer-1 aggregation, fused bias+relu+(@W2) ----------------
__global__ __launch_bounds__(256) void k_agg1(const float* __restrict__ b1,
                                              const float* __restrict__ W2) {
    __shared__ float w2s[HID * 2];
    int t = threadIdx.x;
    w2s[t] = W2[t];
    __syncthreads();

    int warp = t >> 5, lane = t & 31;
    int i = blockIdx.x * 8 + warp;
    if (i >= NN) return;

    const uint2* xw2 = (const uint2*)g_xw;
    float di = g_dinv[i];
    float sn = di * di;
    uint2 sv = xw2[(size_t)i * 32 + lane];
    float2 s0 = __half22float2(*(__half2*)&sv.x);
    float2 s1 = __half22float2(*(__half2*)&sv.y);
    float a0 = sn * s0.x, a1 = sn * s0.y, a2 = sn * s1.x, a3 = sn * s1.y;

    int e = g_rowptr[i];
    int end = e + g_deg[i];
    for (; e + 4 <= end; e += 4) {
        int2 c0 = g_csr[e],     c1 = g_csr[e + 1];
        int2 c2 = g_csr[e + 2], c3 = g_csr[e + 3];
        uint2 v0 = xw2[(size_t)c0.x * 32 + lane];
        uint2 v1 = xw2[(size_t)c1.x * 32 + lane];
        uint2 v2 = xw2[(size_t)c2.x * 32 + lane];
        uint2 v3 = xw2[(size_t)c3.x * 32 + lane];
        float wa = __int_as_float(c0.y), wb = __int_as_float(c1.y);
        float wc_ = __int_as_float(c2.y), wd = __int_as_float(c3.y);
        float2 f;
        f = __half22float2(*(__half2*)&v0.x); a0 += wa * f.x; a1 += wa * f.y;
        f = __half22float2(*(__half2*)&v0.y); a2 += wa * f.x; a3 += wa * f.y;
        f = __half22float2(*(__half2*)&v1.x); a0 += wb * f.x; a1 += wb * f.y;
        f = __half22float2(*(__half2*)&v1.y); a2 += wb * f.x; a3 += wb * f.y;
        f = __half22float2(*(__half2*)&v2.x); a0 += wc_ * f.x; a1 += wc_ * f.y;
        f = __half22float2(*(__half2*)&v2.y); a2 += wc_ * f.x; a3 += wc_ * f.y;
        f = __half22float2(*(__half2*)&v3.x); a0 += wd * f.x; a1 += wd * f.y;
        f = __half22float2(*(__half2*)&v3.y); a2 += wd * f.x; a3 += wd * f.y;
    }
    for (; e < end; e++) {
        int2 c = g_csr[e];
        float w = __int_as_float(c.y);
        uint2 v = xw2[(size_t)c.x * 32 + lane];
        float2 f;
        f = __half22float2(*(__half2*)&v.x); a0 += w * f.x; a1 += w * f.y;
        f = __half22float2(*(__half2*)&v.y); a2 += w * f.x; a3 += w * f.y;
    }

    float4 bb = ((const float4*)b1)[lane];
    float h0 = fmaxf(a0 + bb.x, 0.f);
    float h1 = fmaxf(a1 + bb.y, 0.f);
    float h2 = fmaxf(a2 + bb.z, 0.f);
    float h3 = fmaxf(a3 + bb.w, 0.f);

    int c = lane * 4;
    float z0 = h0 * w2s[(c + 0) * 2 + 0] + h1 * w2s[(c + 1) * 2 + 0]
             + h2 * w2s[(c + 2) * 2 + 0] + h3 * w2s[(c + 3) * 2 + 0];
    float z1 = h0 * w2s[(c + 0) * 2 + 1] + h1 * w2s[(c + 1) * 2 + 1]
             + h2 * w2s[(c + 2) * 2 + 1] + h3 * w2s[(c + 3) * 2 + 1];
    #pragma unroll
    for (int off = 16; off > 0; off >>= 1) {
        z0 += __shfl_down_sync(0xffffffffu, z0, off);
        z1 += __shfl_down_sync(0xffffffffu, z1, off);
    }
    if (lane == 0) ((float2*)g_z)[i] = make_float2(z0, z1);
}

// ---------------- layer-2 aggregation + Wc + sigmoid ----------------
__global__ void k_agg2(const float* __restrict__ b2, const float* __restrict__ Wc,
                       const float* __restrict__ bc, float* __restrict__ out) {
    int i = blockIdx.x * blockDim.x + threadIdx.x;
    if (i >= NN) return;
    const float2* z2 = (const float2*)g_z;
    float di = g_dinv[i];
    float sn = di * di;
    float2 zi = z2[i];
    float a0 = zi.x * sn, a1 = zi.y * sn;
    int e = g_rowptr[i];
    int end = e + g_deg[i];
    for (; e < end; e++) {
        int2 c = g_csr[e];
        float w = __int_as_float(c.y);
        float2 zs = z2[c.x];
        a0 += w * zs.x;
        a1 += w * zs.y;
    }
    float h0 = fmaxf(a0 + b2[0], 0.f);
    float h1 = fmaxf(a1 + b2[1], 0.f);
    float o = h0 * Wc[0] + h1 * Wc[1] + bc[0];
    out[i] = 1.f / (1.f + expf(-o));
}

// ---------------- launch (single stream, no host objects) ----------------
extern "C" void kernel_launch(void* const* d_in, const int* in_sizes, int n_in,
                              void* d_out, int out_size) {
    const float* x  = (const float*)d_in[0];
    const int*   ei = (const int*)d_in[1];
    const float* W1 = (const float*)d_in[2];
    const float* b1 = (const float*)d_in[3];
    const float* W2 = (const float*)d_in[4];
    const float* b2 = (const float*)d_in[5];
    const float* Wc = (const float*)d_in[6];
    const float* bc = (const float*)d_in[7];
    float* out = (float*)d_out;

    k_init<<<(NN + 255) / 256, 256>>>();
    k_count<<<(NE / 4 + 255) / 256, 256>>>(ei);
    k_scan<<<NBT, 512>>>();
    k_fill_gemm<<<GEMM_NB + FILL_NB, 256>>>(ei, x, W1);
    k_agg1<<<(NN + 7) / 8, 256>>>(b1, W2);
    k_agg2<<<(NN + 255) / 256, 256>>>(b2, Wc, bc, out);
}

// round 7
// speedup vs baseline: 1.4164x; 1.1483x over previous
#include <cuda_runtime.h>
#include <cuda_fp16.h>
#include <cuda_bf16.h>
#include <mma.h>
#include <math.h>

using namespace nvcuda;

#define NN 100000
#define NE 1600000
#define FEAT 165
#define HID 128
#define NBT 196          // scan tiles (196 * 512 >= NN)
#define GEMM_NB 1563     // ceil(100000/64)
#define FILL_NB 782      // 782*256 threads * 8 edges >= NE

// ---------------- scratch (static __device__, allocation-free) ----------------
__device__ int      g_deg[NN];
__device__ float    g_dinv[NN];
__device__ int      g_rowptr[NN];
__device__ int      g_cursor[NN];
__device__ int      g_tile_ctr;
__device__ unsigned g_tile_state[NBT];
__device__ int2     g_csr[NE];              // (src, bits(w))
__device__ __half   g_xw[(size_t)NN * HID]; // x @ W1 in fp16 (25.6 MB)
__device__ float    g_z[NN * 2];

#define ST_AGG 0x40000000u
#define ST_PRE 0x80000000u
#define ST_VAL 0x3FFFFFFFu

// ---------------- init: zero degrees + scan state ----------------
__global__ void k_init() {
    int i = blockIdx.x * blockDim.x + threadIdx.x;
    if (i < NN) g_deg[i] = 0;
    if (i < NBT) g_tile_state[i] = 0;
    if (i == 0) g_tile_ctr = 0;
}

// 4 edges per thread, int4 edge reads
__global__ void k_count(const int* __restrict__ ei) {
    int t = blockIdx.x * blockDim.x + threadIdx.x;
    int e0 = t * 4;
    if (e0 < NE) {
        int4 d4 = *(const int4*)&ei[NE + e0];
        if (d4.x >= 0 && d4.x < NN) atomicAdd(&g_deg[d4.x], 1);
        if (d4.y >= 0 && d4.y < NN) atomicAdd(&g_deg[d4.y], 1);
        if (d4.z >= 0 && d4.z < NN) atomicAdd(&g_deg[d4.z], 1);
        if (d4.w >= 0 && d4.w < NN) atomicAdd(&g_deg[d4.w], 1);
    }
}

// ---------------- single-pass scan (decoupled lookback) + dinv ----------------
__global__ void k_scan() {
    __shared__ int s[512];
    __shared__ int sh_bid;
    __shared__ int sh_excl;
    int t = threadIdx.x;
    if (t == 0) sh_bid = atomicAdd(&g_tile_ctr, 1);
    __syncthreads();
    int bid = sh_bid;
    int i = bid * 512 + t;
    int v = (i < NN) ? g_deg[i] : 0;
    if (i < NN) g_dinv[i] = rsqrtf((float)v + 1.0f);
    s[t] = v;
    __syncthreads();
    #pragma unroll
    for (int off = 1; off < 512; off <<= 1) {
        int u = (t >= off) ? s[t - off] : 0;
        __syncthreads();
        s[t] += u;
        __syncthreads();
    }
    int incl = s[t];
    int total = s[511];
    if (t == 0) {
        if (bid == 0) {
            __threadfence();
            atomicExch(&g_tile_state[0], ST_PRE | (unsigned)total);
            sh_excl = 0;
        } else {
            __threadfence();
            atomicExch(&g_tile_state[bid], ST_AGG | (unsigned)total);
            int excl = 0;
            for (int j = bid - 1; j >= 0; j--) {
                unsigned st;
                do { st = atomicAdd(&g_tile_state[j], 0u); } while (!(st & (ST_AGG | ST_PRE)));
                excl += (int)(st & ST_VAL);
                if (st & ST_PRE) break;
            }
            __threadfence();
            atomicExch(&g_tile_state[bid], ST_PRE | (unsigned)(excl + total));
            sh_excl = excl;
        }
    }
    __syncthreads();
    if (i < NN) {
        int rp = sh_excl + incl - v;
        g_rowptr[i] = rp;
        g_cursor[i] = rp;
    }
}

// ---------------- fused fill + GEMM1 (bf16 wmma, light regs) ----------------
// GEMM: block tile 64x128, 8 warps each 16x64, K-tile 32 (2 mma k-steps)
#define ASTR 40
#define BSTR 136

__global__ __launch_bounds__(256, 2) void k_fill_gemm(const int* __restrict__ ei,
                                                      const float* __restrict__ x,
                                                      const float* __restrict__ W1) {
    __shared__ __nv_bfloat16 As[64 * ASTR];   // 5.1 KB
    __shared__ __nv_bfloat16 Bs[32 * BSTR];   // 8.7 KB
    __shared__ float Cs[8][16 * 64];          // 32 KB per-warp C stage

    int tid = threadIdx.x;

    if (blockIdx.x >= GEMM_NB) {
        // ---------- fill branch: 8 edges per thread, int4 reads ----------
        int t8 = (blockIdx.x - GEMM_NB) * 256 + tid;
        int e0 = t8 * 8;
        if (e0 < NE) {
            int4 sa = *(const int4*)&ei[e0];
            int4 sb = *(const int4*)&ei[e0 + 4];
            int4 da = *(const int4*)&ei[NE + e0];
            int4 db = *(const int4*)&ei[NE + e0 + 4];
            int src[8] = {sa.x, sa.y, sa.z, sa.w, sb.x, sb.y, sb.z, sb.w};
            int dst[8] = {da.x, da.y, da.z, da.w, db.x, db.y, db.z, db.w};
            float ds[8], dd[8];
            #pragma unroll
            for (int j = 0; j < 8; j++) {
                bool ok = (src[j] >= 0 && src[j] < NN && dst[j] >= 0 && dst[j] < NN);
                ds[j] = ok ? g_dinv[src[j]] : 0.f;
                dd[j] = ok ? g_dinv[dst[j]] : 0.f;
                if (!ok) dst[j] = -1;
            }
            #pragma unroll
            for (int j = 0; j < 8; j++) {
                if (dst[j] >= 0) {
                    int p = atomicAdd(&g_cursor[dst[j]], 1);
                    g_csr[p] = make_int2(src[j], __float_as_int(ds[j] * dd[j]));
                }
            }
        }
        return;
    }

    // ---------- GEMM branch ----------
    int w = tid >> 5;
    int lane = tid & 31;
    int warp_m = w & 3;        // 0..3 -> 16-row band (64 rows total)
    int warp_n = w >> 2;       // 0..1 -> 64-col band
    int row0 = blockIdx.x * 64;

    wmma::fragment<wmma::accumulator, 16, 16, 16, float> cf[4];
    #pragma unroll
    for (int ni = 0; ni < 4; ni++) wmma::fill_fragment(cf[ni], 0.0f);

    for (int k0 = 0; k0 < FEAT; k0 += 32) {
        // As[m][k] = bf16(x[row0+m][k0+k])  : 2048 elems, 8 per thread
        #pragma unroll
        for (int i = 0; i < 8; i++) {
            int idx = tid + i * 256;
            int m = idx >> 5, k = idx & 31;
            int r = row0 + m, kk = k0 + k;
            float v = (r < NN && kk < FEAT) ? x[(size_t)r * FEAT + kk] : 0.f;
            As[m * ASTR + k] = __float2bfloat16(v);
        }
        // Bs[k][n] = bf16(W1[k0+k][n])      : 4096 elems, 16 per thread
        #pragma unroll
        for (int i = 0; i < 16; i++) {
            int idx = tid + i * 256;
            int k = idx >> 7, n = idx & 127;
            int kk = k0 + k;
            float v = (kk < FEAT) ? W1[kk * HID + n] : 0.f;
            Bs[k * BSTR + n] = __float2bfloat16(v);
        }
        __syncthreads();
        #pragma unroll
        for (int ks = 0; ks < 2; ks++) {
            wmma::fragment<wmma::matrix_a, 16, 16, 16, __nv_bfloat16, wmma::row_major> af;
            wmma::fragment<wmma::matrix_b, 16, 16, 16, __nv_bfloat16, wmma::row_major> bf[4];
            wmma::load_matrix_sync(af, As + (warp_m * 16) * ASTR + ks * 16, ASTR);
            #pragma unroll
            for (int ni = 0; ni < 4; ni++)
                wmma::load_matrix_sync(bf[ni], Bs + (ks * 16) * BSTR + warp_n * 64 + ni * 16, BSTR);
            #pragma unroll
            for (int ni = 0; ni < 4; ni++)
                wmma::mma_sync(cf[ni], af, bf[ni], cf[ni]);
        }
        __syncthreads();
    }

    // epilogue: stage warp's 16x64 C in smem, convert to fp16, store
    #pragma unroll
    for (int ni = 0; ni < 4; ni++)
        wmma::store_matrix_sync(&Cs[w][ni * 16], cf[ni], 64, wmma::mem_row_major);
    __syncwarp();

    int fr = lane >> 1;                 // 0..15
    int cstart = (lane & 1) * 32;       // 0 or 32
    int r = row0 + warp_m * 16 + fr;
    if (r < NN) {
        #pragma unroll
        for (int c = 0; c < 4; c++) {
            const float* src = &Cs[w][fr * 64 + cstart + c * 8];
            __half2 h0 = __floats2half2_rn(src[0], src[1]);
            __half2 h1 = __floats2half2_rn(src[2], src[3]);
            __half2 h2 = __floats2half2_rn(src[4], src[5]);
            __half2 h3 = __floats2half2_rn(src[6], src[7]);
            uint4 pk;
            pk.x = *(unsigned*)&h0; pk.y = *(unsigned*)&h1;
            pk.z = *(unsigned*)&h2; pk.w = *(unsigned*)&h3;
            *(uint4*)&g_xw[(size_t)r * HID + warp_n * 64 + cstart + c * 8] = pk;
        }
    }
}

// ---------------- layer-1 aggregation, fused bias+relu+(@W2) ----------------
__global__ __launch_bounds__(256) void k_agg1(const float* __restrict__ b1,
                                              const float* __restrict__ W2) {
    __shared__ float w2s[HID * 2];
    int t = threadIdx.x;
    w2s[t] = W2[t];
    __syncthreads();

    int warp = t >> 5, lane = t & 31;
    int i = blockIdx.x * 8 + warp;
    if (i >= NN) return;

    const uint2* xw2 = (const uint2*)g_xw;
    float di = g_dinv[i];
    float sn = di * di;
    uint2 sv = xw2[(size_t)i * 32 + lane];
    float2 s0 = __half22float2(*(__half2*)&sv.x);
    float2 s1 = __half22float2(*(__half2*)&sv.y);
    float a0 = sn * s0.x, a1 = sn * s0.y, a2 = sn * s1.x, a3 = sn * s1.y;

    int e = g_rowptr[i];
    int end = e + g_deg[i];
    for (; e + 4 <= end; e += 4) {
        int2 c0 = g_csr[e],     c1 = g_csr[e + 1];
        int2 c2 = g_csr[e + 2], c3 = g_csr[e + 3];
        uint2 v0 = xw2[(size_t)c0.x * 32 + lane];
        uint2 v1 = xw2[(size_t)c1.x * 32 + lane];
        uint2 v2 = xw2[(size_t)c2.x * 32 + lane];
        uint2 v3 = xw2[(size_t)c3.x * 32 + lane];
        float wa = __int_as_float(c0.y), wb = __int_as_float(c1.y);
        float wc_ = __int_as_float(c2.y), wd = __int_as_float(c3.y);
        float2 f;
        f = __half22float2(*(__half2*)&v0.x); a0 += wa * f.x; a1 += wa * f.y;
        f = __half22float2(*(__half2*)&v0.y); a2 += wa * f.x; a3 += wa * f.y;
        f = __half22float2(*(__half2*)&v1.x); a0 += wb * f.x; a1 += wb * f.y;
        f = __half22float2(*(__half2*)&v1.y); a2 += wb * f.x; a3 += wb * f.y;
        f = __half22float2(*(__half2*)&v2.x); a0 += wc_ * f.x; a1 += wc_ * f.y;
        f = __half22float2(*(__half2*)&v2.y); a2 += wc_ * f.x; a3 += wc_ * f.y;
        f = __half22float2(*(__half2*)&v3.x); a0 += wd * f.x; a1 += wd * f.y;
        f = __half22float2(*(__half2*)&v3.y); a2 += wd * f.x; a3 += wd * f.y;
    }
    for (; e < end; e++) {
        int2 c = g_csr[e];
        float w = __int_as_float(c.y);
        uint2 v = xw2[(size_t)c.x * 32 + lane];
        float2 f;
        f = __half22float2(*(__half2*)&v.x); a0 += w * f.x; a1 += w * f.y;
        f = __half22float2(*(__half2*)&v.y); a2 += w * f.x; a3 += w * f.y;
    }

    float4 bb = ((const float4*)b1)[lane];
    float h0 = fmaxf(a0 + bb.x, 0.f);
    float h1 = fmaxf(a1 + bb.y, 0.f);
    float h2 = fmaxf(a2 + bb.z, 0.f);
    float h3 = fmaxf(a3 + bb.w, 0.f);

    int c = lane * 4;
    float z0 = h0 * w2s[(c + 0) * 2 + 0] + h1 * w2s[(c + 1) * 2 + 0]
             + h2 * w2s[(c + 2) * 2 + 0] + h3 * w2s[(c + 3) * 2 + 0];
    float z1 = h0 * w2s[(c + 0) * 2 + 1] + h1 * w2s[(c + 1) * 2 + 1]
             + h2 * w2s[(c + 2) * 2 + 1] + h3 * w2s[(c + 3) * 2 + 1];
    #pragma unroll
    for (int off = 16; off > 0; off >>= 1) {
        z0 += __shfl_down_sync(0xffffffffu, z0, off);
        z1 += __shfl_down_sync(0xffffffffu, z1, off);
    }
    if (lane == 0) ((float2*)g_z)[i] = make_float2(z0, z1);
}

// ---------------- layer-2 aggregation + Wc + sigmoid ----------------
__global__ void k_agg2(const float* __restrict__ b2, const float* __restrict__ Wc,
                       const float* __restrict__ bc, float* __restrict__ out) {
    int i = blockIdx.x * blockDim.x + threadIdx.x;
    if (i >= NN) return;
    const float2* z2 = (const float2*)g_z;
    float di = g_dinv[i];
    float sn = di * di;
    float2 zi = z2[i];
    float a0 = zi.x * sn, a1 = zi.y * sn;
    int e = g_rowptr[i];
    int end = e + g_deg[i];
    for (; e < end; e++) {
        int2 c = g_csr[e];
        float w = __int_as_float(c.y);
        float2 zs = z2[c.x];
        a0 += w * zs.x;
        a1 += w * zs.y;
    }
    float h0 = fmaxf(a0 + b2[0], 0.f);
    float h1 = fmaxf(a1 + b2[1], 0.f);
    float o = h0 * Wc[0] + h1 * Wc[1] + bc[0];
    out[i] = 1.f / (1.f + expf(-o));
}

// ---------------- launch (single stream, no host objects) ----------------
extern "C" void kernel_launch(void* const* d_in, const int* in_sizes, int n_in,
                              void* d_out, int out_size) {
    const float* x  = (const float*)d_in[0];
    const int*   ei = (const int*)d_in[1];
    const float* W1 = (const float*)d_in[2];
    const float* b1 = (const float*)d_in[3];
    const float* W2 = (const float*)d_in[4];
    const float* b2 = (const float*)d_in[5];
    const float* Wc = (const float*)d_in[6];
    const float* bc = (const float*)d_in[7];
    float* out = (float*)d_out;

    k_init<<<(NN + 255) / 256, 256>>>();
    k_count<<<(NE / 4 + 255) / 256, 256>>>(ei);
    k_scan<<<NBT, 512>>>();
    k_fill_gemm<<<GEMM_NB + FILL_NB, 256>>>(ei, x, W1);
    k_agg1<<<(NN + 7) / 8, 256>>>(b1, W2);
    k_agg2<<<(NN + 255) / 256, 256>>>(b2, Wc, bc, out);
}

// round 8
// speedup vs baseline: 1.6983x; 1.1990x over previous
#include <cuda_runtime.h>
#include <cuda_fp16.h>
#include <cuda_bf16.h>
#include <mma.h>
#include <math.h>

using namespace nvcuda;

#define NN 100000
#define NE 1600000
#define FEAT 165
#define HID 128
#define NBT 196          // scan tiles (196 * 512 >= NN)
#define GEMM_NB 782      // ceil(100000/128)
#define FILL_NB 782      // 782*256 threads * 8 edges >= NE

// ---------------- scratch (static __device__, allocation-free) ----------------
__device__ int      g_deg[NN];
__device__ float    g_dinv[NN];
__device__ int      g_rowptr[NN];
__device__ int      g_cursor[NN];
__device__ int      g_tile_ctr;
__device__ unsigned g_tile_state[NBT];
__device__ int2     g_csr[NE];              // (src, bits(w))
__device__ __half   g_xw[(size_t)NN * HID]; // x @ W1 in fp16 (25.6 MB)
__device__ float    g_z[NN * 2];

#define ST_AGG 0x40000000u
#define ST_PRE 0x80000000u
#define ST_VAL 0x3FFFFFFFu

// ---------------- init: zero degrees + scan state ----------------
__global__ void k_init() {
    int i = blockIdx.x * blockDim.x + threadIdx.x;
    if (i < NN) g_deg[i] = 0;
    if (i < NBT) g_tile_state[i] = 0;
    if (i == 0) g_tile_ctr = 0;
}

// 4 edges per thread, int4 edge reads
__global__ void k_count(const int* __restrict__ ei) {
    int t = blockIdx.x * blockDim.x + threadIdx.x;
    int e0 = t * 4;
    if (e0 < NE) {
        int4 d4 = *(const int4*)&ei[NE + e0];
        if (d4.x >= 0 && d4.x < NN) atomicAdd(&g_deg[d4.x], 1);
        if (d4.y >= 0 && d4.y < NN) atomicAdd(&g_deg[d4.y], 1);
        if (d4.z >= 0 && d4.z < NN) atomicAdd(&g_deg[d4.z], 1);
        if (d4.w >= 0 && d4.w < NN) atomicAdd(&g_deg[d4.w], 1);
    }
}

// ---------------- single-pass scan (decoupled lookback) + dinv ----------------
__global__ void k_scan() {
    __shared__ int s[512];
    __shared__ int sh_bid;
    __shared__ int sh_excl;
    int t = threadIdx.x;
    if (t == 0) sh_bid = atomicAdd(&g_tile_ctr, 1);
    __syncthreads();
    int bid = sh_bid;
    int i = bid * 512 + t;
    int v = (i < NN) ? g_deg[i] : 0;
    if (i < NN) g_dinv[i] = rsqrtf((float)v + 1.0f);
    s[t] = v;
    __syncthreads();
    #pragma unroll
    for (int off = 1; off < 512; off <<= 1) {
        int u = (t >= off) ? s[t - off] : 0;
        __syncthreads();
        s[t] += u;
        __syncthreads();
    }
    int incl = s[t];
    int total = s[511];
    if (t == 0) {
        if (bid == 0) {
            __threadfence();
            atomicExch(&g_tile_state[0], ST_PRE | (unsigned)total);
            sh_excl = 0;
        } else {
            __threadfence();
            atomicExch(&g_tile_state[bid], ST_AGG | (unsigned)total);
            int excl = 0;
            for (int j = bid - 1; j >= 0; j--) {
                unsigned st;
                do { st = atomicAdd(&g_tile_state[j], 0u); } while (!(st & (ST_AGG | ST_PRE)));
                excl += (int)(st & ST_VAL);
                if (st & ST_PRE) break;
            }
            __threadfence();
            atomicExch(&g_tile_state[bid], ST_PRE | (unsigned)(excl + total));
            sh_excl = excl;
        }
    }
    __syncthreads();
    if (i < NN) {
        int rp = sh_excl + incl - v;
        g_rowptr[i] = rp;
        g_cursor[i] = rp;
    }
}

// ---------------- fused fill + GEMM1 (bf16 wmma, 128x128 tile) --------------
// GEMM: block 128x128, 8 warps each 32x64 (2x4 fragments), K-tile 32
#define ASTR 40
#define BSTR 136

__global__ __launch_bounds__(256, 2) void k_fill_gemm(const int* __restrict__ ei,
                                                      const float* __restrict__ x,
                                                      const float* __restrict__ W1) {
    __shared__ __nv_bfloat16 As[128 * ASTR];  // 10.0 KB
    __shared__ __nv_bfloat16 Bs[32 * BSTR];   // 8.5 KB
    __shared__ float Cs[8][16 * 16];          // 8 KB per-warp fragment stage

    int tid = threadIdx.x;

    if (blockIdx.x >= GEMM_NB) {
        // ---------- fill branch: 8 edges per thread, int4 reads ----------
        int t8 = (blockIdx.x - GEMM_NB) * 256 + tid;
        int e0 = t8 * 8;
        if (e0 < NE) {
            int4 sa = *(const int4*)&ei[e0];
            int4 sb = *(const int4*)&ei[e0 + 4];
            int4 da = *(const int4*)&ei[NE + e0];
            int4 db = *(const int4*)&ei[NE + e0 + 4];
            int src[8] = {sa.x, sa.y, sa.z, sa.w, sb.x, sb.y, sb.z, sb.w};
            int dst[8] = {da.x, da.y, da.z, da.w, db.x, db.y, db.z, db.w};
            float ds[8], dd[8];
            #pragma unroll
            for (int j = 0; j < 8; j++) {
                bool ok = (src[j] >= 0 && src[j] < NN && dst[j] >= 0 && dst[j] < NN);
                ds[j] = ok ? g_dinv[src[j]] : 0.f;
                dd[j] = ok ? g_dinv[dst[j]] : 0.f;
                if (!ok) dst[j] = -1;
            }
            #pragma unroll
            for (int j = 0; j < 8; j++) {
                if (dst[j] >= 0) {
                    int p = atomicAdd(&g_cursor[dst[j]], 1);
                    g_csr[p] = make_int2(src[j], __float_as_int(ds[j] * dd[j]));
                }
            }
        }
        return;
    }

    // ---------- GEMM branch ----------
    int w = tid >> 5;
    int lane = tid & 31;
    int warp_m = w & 3;        // 0..3 -> 32-row band
    int warp_n = w >> 2;       // 0..1 -> 64-col band
    int row0 = blockIdx.x * 128;

    wmma::fragment<wmma::accumulator, 16, 16, 16, float> cf[2][4];
    #pragma unroll
    for (int mi = 0; mi < 2; mi++)
        #pragma unroll
        for (int ni = 0; ni < 4; ni++)
            wmma::fill_fragment(cf[mi][ni], 0.0f);

    for (int k0 = 0; k0 < FEAT; k0 += 32) {
        // As[m][k] = bf16(x[row0+m][k0+k]) : 4096 elems, 16 per thread (coalesced)
        #pragma unroll
        for (int i = 0; i < 16; i++) {
            int idx = tid + i * 256;
            int m = idx >> 5, k = idx & 31;
            int r = row0 + m, kk = k0 + k;
            float v = (r < NN && kk < FEAT) ? x[(size_t)r * FEAT + kk] : 0.f;
            As[m * ASTR + k] = __float2bfloat16(v);
        }
        // Bs[k][n] = bf16(W1[k0+k][n]) : 4096 elems, float4 loads, 4/thread
        #pragma unroll
        for (int i = 0; i < 4; i++) {
            int flat = (tid + i * 256) * 4;
            int k = flat >> 7, n = flat & 127;
            int kk = k0 + k;
            float4 v = (kk < FEAT) ? *(const float4*)&W1[kk * HID + n]
                                   : make_float4(0.f, 0.f, 0.f, 0.f);
            __nv_bfloat16* bp = &Bs[k * BSTR + n];
            bp[0] = __float2bfloat16(v.x);
            bp[1] = __float2bfloat16(v.y);
            bp[2] = __float2bfloat16(v.z);
            bp[3] = __float2bfloat16(v.w);
        }
        __syncthreads();
        #pragma unroll
        for (int ks = 0; ks < 2; ks++) {
            wmma::fragment<wmma::matrix_a, 16, 16, 16, __nv_bfloat16, wmma::row_major> af[2];
            wmma::fragment<wmma::matrix_b, 16, 16, 16, __nv_bfloat16, wmma::row_major> bf[4];
            #pragma unroll
            for (int mi = 0; mi < 2; mi++)
                wmma::load_matrix_sync(af[mi], As + (warp_m * 32 + mi * 16) * ASTR + ks * 16, ASTR);
            #pragma unroll
            for (int ni = 0; ni < 4; ni++)
                wmma::load_matrix_sync(bf[ni], Bs + (ks * 16) * BSTR + warp_n * 64 + ni * 16, BSTR);
            #pragma unroll
            for (int mi = 0; mi < 2; mi++)
                #pragma unroll
                for (int ni = 0; ni < 4; ni++)
                    wmma::mma_sync(cf[mi][ni], af[mi], bf[ni], cf[mi][ni]);
        }
        __syncthreads();
    }

    // epilogue: per-fragment smem stage -> fp16 global
    #pragma unroll
    for (int mi = 0; mi < 2; mi++) {
        #pragma unroll
        for (int ni = 0; ni < 4; ni++) {
            wmma::store_matrix_sync(Cs[w], cf[mi][ni], 16, wmma::mem_row_major);
            __syncwarp();
            int fr = lane >> 1;            // 0..15
            int fc = (lane & 1) * 8;       // 0 or 8
            int r = row0 + warp_m * 32 + mi * 16 + fr;
            if (r < NN) {
                const float* src = &Cs[w][fr * 16 + fc];
                __half2 h0 = __floats2half2_rn(src[0], src[1]);
                __half2 h1 = __floats2half2_rn(src[2], src[3]);
                __half2 h2 = __floats2half2_rn(src[4], src[5]);
                __half2 h3 = __floats2half2_rn(src[6], src[7]);
                uint4 pk;
                pk.x = *(unsigned*)&h0; pk.y = *(unsigned*)&h1;
                pk.z = *(unsigned*)&h2; pk.w = *(unsigned*)&h3;
                *(uint4*)&g_xw[(size_t)r * HID + warp_n * 64 + ni * 16 + fc] = pk;
            }
            __syncwarp();
        }
    }
}

// ---------------- layer-1 aggregation, fused bias+relu+(@W2) ----------------
__global__ __launch_bounds__(256) void k_agg1(const float* __restrict__ b1,
                                              const float* __restrict__ W2) {
    __shared__ float w2s[HID * 2];
    int t = threadIdx.x;
    w2s[t] = W2[t];
    __syncthreads();

    int warp = t >> 5, lane = t & 31;
    int i = blockIdx.x * 8 + warp;
    if (i >= NN) return;

    const uint2* xw2 = (const uint2*)g_xw;
    float di = g_dinv[i];
    float sn = di * di;
    uint2 sv = xw2[(size_t)i * 32 + lane];
    float2 s0 = __half22float2(*(__half2*)&sv.x);
    float2 s1 = __half22float2(*(__half2*)&sv.y);
    float a0 = sn * s0.x, a1 = sn * s0.y, a2 = sn * s1.x, a3 = sn * s1.y;

    int e = g_rowptr[i];
    int end = e + g_deg[i];
    for (; e + 4 <= end; e += 4) {
        int2 c0 = g_csr[e],     c1 = g_csr[e + 1];
        int2 c2 = g_csr[e + 2], c3 = g_csr[e + 3];
        uint2 v0 = xw2[(size_t)c0.x * 32 + lane];
        uint2 v1 = xw2[(size_t)c1.x * 32 + lane];
        uint2 v2 = xw2[(size_t)c2.x * 32 + lane];
        uint2 v3 = xw2[(size_t)c3.x * 32 + lane];
        float wa = __int_as_float(c0.y), wb = __int_as_float(c1.y);
        float wc_ = __int_as_float(c2.y), wd = __int_as_float(c3.y);
        float2 f;
        f = __half22float2(*(__half2*)&v0.x); a0 += wa * f.x; a1 += wa * f.y;
        f = __half22float2(*(__half2*)&v0.y); a2 += wa * f.x; a3 += wa * f.y;
        f = __half22float2(*(__half2*)&v1.x); a0 += wb * f.x; a1 += wb * f.y;
        f = __half22float2(*(__half2*)&v1.y); a2 += wb * f.x; a3 += wb * f.y;
        f = __half22float2(*(__half2*)&v2.x); a0 += wc_ * f.x; a1 += wc_ * f.y;
        f = __half22float2(*(__half2*)&v2.y); a2 += wc_ * f.x; a3 += wc_ * f.y;
        f = __half22float2(*(__half2*)&v3.x); a0 += wd * f.x; a1 += wd * f.y;
        f = __half22float2(*(__half2*)&v3.y); a2 += wd * f.x; a3 += wd * f.y;
    }
    for (; e < end; e++) {
        int2 c = g_csr[e];
        float w = __int_as_float(c.y);
        uint2 v = xw2[(size_t)c.x * 32 + lane];
        float2 f;
        f = __half22float2(*(__half2*)&v.x); a0 += w * f.x; a1 += w * f.y;
        f = __half22float2(*(__half2*)&v.y); a2 += w * f.x; a3 += w * f.y;
    }

    float4 bb = ((const float4*)b1)[lane];
    float h0 = fmaxf(a0 + bb.x, 0.f);
    float h1 = fmaxf(a1 + bb.y, 0.f);
    float h2 = fmaxf(a2 + bb.z, 0.f);
    float h3 = fmaxf(a3 + bb.w, 0.f);

    int c = lane * 4;
    float z0 = h0 * w2s[(c + 0) * 2 + 0] + h1 * w2s[(c + 1) * 2 + 0]
             + h2 * w2s[(c + 2) * 2 + 0] + h3 * w2s[(c + 3) * 2 + 0];
    float z1 = h0 * w2s[(c + 0) * 2 + 1] + h1 * w2s[(c + 1) * 2 + 1]
             + h2 * w2s[(c + 2) * 2 + 1] + h3 * w2s[(c + 3) * 2 + 1];
    #pragma unroll
    for (int off = 16; off > 0; off >>= 1) {
        z0 += __shfl_down_sync(0xffffffffu, z0, off);
        z1 += __shfl_down_sync(0xffffffffu, z1, off);
    }
    if (lane == 0) ((float2*)g_z)[i] = make_float2(z0, z1);
}

// ---------------- layer-2 aggregation + Wc + sigmoid ----------------
__global__ void k_agg2(const float* __restrict__ b2, const float* __restrict__ Wc,
                       const float* __restrict__ bc, float* __restrict__ out) {
    int i = blockIdx.x * blockDim.x + threadIdx.x;
    if (i >= NN) return;
    const float2* z2 = (const float2*)g_z;
    float di = g_dinv[i];
    float sn = di * di;
    float2 zi = z2[i];
    float a0 = zi.x * sn, a1 = zi.y * sn;
    int e = g_rowptr[i];
    int end = e + g_deg[i];
    for (; e < end; e++) {
        int2 c = g_csr[e];
        float w = __int_as_float(c.y);
        float2 zs = z2[c.x];
        a0 += w * zs.x;
        a1 += w * zs.y;
    }
    float h0 = fmaxf(a0 + b2[0], 0.f);
    float h1 = fmaxf(a1 + b2[1], 0.f);
    float o = h0 * Wc[0] + h1 * Wc[1] + bc[0];
    out[i] = 1.f / (1.f + expf(-o));
}

// ---------------- launch (single stream, no host objects) ----------------
extern "C" void kernel_launch(void* const* d_in, const int* in_sizes, int n_in,
                              void* d_out, int out_size) {
    const float* x  = (const float*)d_in[0];
    const int*   ei = (const int*)d_in[1];
    const float* W1 = (const float*)d_in[2];
    const float* b1 = (const float*)d_in[3];
    const float* W2 = (const float*)d_in[4];
    const float* b2 = (const float*)d_in[5];
    const float* Wc = (const float*)d_in[6];
    const float* bc = (const float*)d_in[7];
    float* out = (float*)d_out;

    k_init<<<(NN + 255) / 256, 256>>>();
    k_count<<<(NE / 4 + 255) / 256, 256>>>(ei);
    k_scan<<<NBT, 512>>>();
    k_fill_gemm<<<GEMM_NB + FILL_NB, 256>>>(ei, x, W1);
    k_agg1<<<(NN + 7) / 8, 256>>>(b1, W2);
    k_agg2<<<(NN + 255) / 256, 256>>>(b2, Wc, bc, out);
}